// round 16
// baseline (speedup 1.0000x reference)
#include <cuda_runtime.h>
#include <math.h>
#include <stdint.h>

#define NSAMP   32768
#define NSIG    16          // 8 target + 8 recon
#define NBANDS  7
#define NFILT   64
#define KTOP    128
#define BAND_SPAN 65024     // sum of band sizes per signal
#define PBLOCKS 56
#define NCHU    128         // unified chunks per signal: 65+32+16+8+4+2+1

// multi-scale padding: conflict-free strided smem access for all FFT stages
#define PADI(i) ((i) + ((i) >> 4) + ((i) >> 8))

// ---------------- scratch (static device globals; no allocation) -------------
__device__ float2 d_X[NSIG * 16384];                 // rfft bins per signal
__device__ float  d_band[NSIG * BAND_SPAN];          // all band time signals
__device__ float  d_seg [NSIG * NBANDS * NFILT * 65];// segment maxima (65 segs)
__device__ float  d_tkv [NSIG * NBANDS * KTOP];      // top-k values
__device__ int    d_tki [NSIG * NBANDS * KTOP];      // top-k flat indices
__device__ float  d_partial[PBLOCKS];
__device__ float2 d_tab[16384];                      // e^{+2pi i r/32768}

__device__ __forceinline__ int band_off(int j) { return 512 * ((1 << j) - 1); }

__device__ __forceinline__ float2 cmul_s(float2 a, float2 w, float sign) {
    float wy = sign * w.y;
    return make_float2(a.x * w.x - a.y * wy, a.x * wy + a.y * w.x);
}

// ---------------- 0) twiddle table init ---------------------------------------
__global__ void tw_init_kernel() {
    int idx = blockIdx.x * blockDim.x + threadIdx.x;
    if (idx < 16384) {
        float s_, c_;
        sincospif((float)idx / 16384.0f, &s_, &c_);   // 2*pi*idx/32768
        d_tab[idx] = make_float2(c_, s_);
    }
}

// ------------- fused radix-4 (2x radix-2) in-place DIT FFT over smem ----------
__device__ __forceinline__ void fft_fused(float2* a, const float2* tw,
                                          int n, int logn, float sign,
                                          int tid, int T) {
    int st = 1;
    if (logn & 1) {
        int nb = n >> 1;
        for (int idx = tid; idx < nb; idx += T) {
            int i0 = idx << 1;
            int p0 = PADI(i0), p1 = PADI(i0 + 1);
            float2 u = a[p0], v = a[p1];
            a[p0] = make_float2(u.x + v.x, u.y + v.y);
            a[p1] = make_float2(u.x - v.x, u.y - v.y);
        }
        __syncthreads();
        st = 2;
    }
    int nq = n >> 2;
    for (; st < logn; st += 2) {
        int h = 1 << (st - 1);
        int shift = logn - st;
        for (int q = tid; q < nq; q += T) {
            int jj = q & (h - 1);
            int i0 = ((q >> (st - 1)) << (st + 1)) + jj;
            int p0 = PADI(i0), p1 = PADI(i0 + h);
            int p2 = PADI(i0 + 2 * h), p3 = PADI(i0 + 3 * h);
            float2 x0 = a[p0], x1 = a[p1], x2 = a[p2], x3 = a[p3];
            float2 wa = tw[PADI(jj << shift)];
            float2 wb = tw[PADI(jj << (shift - 1))];
            float2 t1 = cmul_s(x1, wa, sign);
            float2 t3 = cmul_s(x3, wa, sign);
            float2 y0 = make_float2(x0.x + t1.x, x0.y + t1.y);
            float2 y1 = make_float2(x0.x - t1.x, x0.y - t1.y);
            float2 y2 = make_float2(x2.x + t3.x, x2.y + t3.y);
            float2 y3 = make_float2(x2.x - t3.x, x2.y - t3.y);
            float2 u2 = cmul_s(y2, wb, sign);
            float2 u3 = cmul_s(y3, wb, sign);
            float2 v3 = make_float2(-sign * u3.y, sign * u3.x);
            a[p0] = make_float2(y0.x + u2.x, y0.y + u2.y);
            a[p2] = make_float2(y0.x - u2.x, y0.y - u2.y);
            a[p1] = make_float2(y1.x + v3.x, y1.y + v3.y);
            a[p3] = make_float2(y1.x - v3.x, y1.y - v3.y);
        }
        __syncthreads();
    }
}

// load twiddles for size-n FFT from the global table (stride = 32768/n)
__device__ __forceinline__ void load_twiddles(float2* tw, int n, int tid, int T) {
    int st = 32768 / n;
    for (int r = tid; r < (n >> 1); r += T)
        tw[PADI(r)] = d_tab[r * st];
}

// ---------------- 1) forward rfft of each 32768-sample signal -----------------
extern __shared__ float2 smem_c[];
#define DATA_PAD 17472

__global__ __launch_bounds__(1024) void fwd_fft_kernel(const float* __restrict__ tgt,
                                                       const float* __restrict__ rec) {
    const int m = 16384, logm = 14;
    int sig = blockIdx.x;
    const float* x = (sig < 8) ? (tgt + (size_t)sig * NSAMP)
                               : (rec + (size_t)(sig - 8) * NSAMP);
    float2* data = smem_c;
    float2* tw   = smem_c + DATA_PAD;
    int tid = threadIdx.x, T = blockDim.x;

    load_twiddles(tw, m, tid, T);
    for (int t = tid; t < m; t += T) {
        int r = (int)(__brev((unsigned)t) >> (32 - logm));
        data[PADI(r)] = make_float2(x[2 * t], x[2 * t + 1]);
    }
    __syncthreads();
    fft_fused(data, tw, m, logm, -1.0f, tid, T);

    for (int k = tid; k < m; k += T) {
        float2 zk = data[PADI(k)];
        float2 zm = data[PADI((m - k) & (m - 1))];
        float2 E = make_float2(0.5f * (zk.x + zm.x), 0.5f * (zk.y - zm.y));
        float2 D = make_float2(0.5f * (zk.x - zm.x), 0.5f * (zk.y + zm.y));
        float2 ph = d_tab[k];                     // e^{+2pi i k/32768}
        float c_ = ph.x, s_ = -ph.y;              // e^{-2pi i k/32768}
        float2 miD = make_float2(D.y, -D.x);
        float tr = miD.x * c_ - miD.y * s_;
        float ti = miD.x * s_ + miD.y * c_;
        d_X[sig * 16384 + k] = make_float2(E.x + tr, E.y + ti);
    }
}

// ---------------- 2) per-band inverse rfft (ortho-scaled) ---------------------
__global__ __launch_bounds__(1024) void inv_band_kernel() {
    int j   = blockIdx.x;
    int sig = blockIdx.y;
    int m = 256 << j, logm = 8 + j;
    int lo = (j == 0) ? 0 : (m >> 1);
    int s2 = 2 * m;
    const float2* X = d_X + sig * 16384;
    float2* data = smem_c;
    float2* tw   = smem_c + DATA_PAD;
    int tid = threadIdx.x, T = blockDim.x;
    int pst = 16384 / m;                          // phase stride for e^{2pi i k/s2}

    load_twiddles(tw, m, tid, T);
    for (int k = tid; k < m; k += T) {
        float2 Xk = (k >= lo) ? X[k] : make_float2(0.f, 0.f);
        int mk = m - k;
        float2 Xm = (mk >= lo && mk < m) ? X[mk] : make_float2(0.f, 0.f);
        float2 E = make_float2(0.5f * (Xk.x + Xm.x), 0.5f * (Xk.y - Xm.y));
        float2 D = make_float2(0.5f * (Xk.x - Xm.x), 0.5f * (Xk.y + Xm.y));
        float2 ph = d_tab[k * pst];               // e^{+2pi i k/s2}
        float c_ = ph.x, s_ = ph.y;
        float2 O = make_float2(D.x * c_ - D.y * s_, D.x * s_ + D.y * c_);
        float2 Z = make_float2(E.x - O.y, E.y + O.x);
        int r = (int)(__brev((unsigned)k) >> (32 - logm));
        data[PADI(r)] = Z;
    }
    __syncthreads();
    fft_fused(data, tw, m, logm, +1.0f, tid, T);

    float scale = 2.0f * rsqrtf((float)s2 * (float)NSAMP);
    float* out = d_band + sig * BAND_SPAN + band_off(j);
    for (int t = tid; t < m; t += T) {
        float2 z = data[PADI(t)];
        out[2 * t]     = scale * z.x;
        out[2 * t + 1] = scale * z.y;
    }
}

// ---------------- 3) 64-tap FIR + segment maxima, packed f32x2 ----------------
// Taps in REGISTERS (one row per thread), duplicated to f32x2 via mov.b64.
#define FMA2(acc, a, b) asm("fma.rn.f32x2 %0, %1, %2, %3;" \
    : "=l"(acc) : "l"(a), "l"(b), "l"(acc))
#define DUP2(d, x) asm("mov.b64 %0, {%1, %1};" : "=l"(d) : "r"(__float_as_uint(x)))

template<int P>
__device__ __forceinline__ float conv_block(const unsigned long long* __restrict__ tilU,
                                            const float* __restrict__ tap,
                                            int rel, int base, int s) {
    unsigned long long W[P + 1], S[P], T[P + 1];
#pragma unroll
    for (int m = 0; m <= P; m++) W[m] = tilU[rel - 1 + m];
#pragma unroll
    for (int p = 0; p < P; p++) S[p] = 0ull;
#pragma unroll
    for (int p = 0; p <= P; p++) T[p] = 0ull;
#pragma unroll
    for (int h = 0; h < 32; h++) {
        unsigned long long te, to;
        DUP2(te, tap[2 * h]);
        DUP2(to, tap[2 * h + 1]);
#pragma unroll
        for (int p = 0; p < P; p++) FMA2(S[p], W[p + 1], te);
#pragma unroll
        for (int p = 0; p <= P; p++) FMA2(T[p], W[p], to);
        if (h < 31) {
#pragma unroll
            for (int m = P; m >= 1; m--) W[m] = W[m - 1];
            W[0] = tilU[rel - h - 2];
        }
    }
    float mx = -INFINITY;
#pragma unroll
    for (int p = 0; p < P; p++) {
        float2 sv = *(float2*)&S[p];
        float2 ta = *(float2*)&T[p];
        float2 tb = *(float2*)&T[p + 1];
        float v0 = sv.x + ta.y;
        float v1 = sv.y + tb.x;
        int ia = base + 2 * p;
        if (ia < 0 || ia >= s)         v0 = -INFINITY;
        if (ia + 1 < 0 || ia + 1 >= s) v1 = -INFINITY;
        mx = fmaxf(mx, fmaxf(v0, v1));
    }
    return mx;
}

// runner: cnt == 8 or a multiple of 16 (only <4>/<8> instantiated)
__device__ __forceinline__ float conv_run(const unsigned long long* __restrict__ tilU,
                                          const float* __restrict__ tap,
                                          int i0, int o0, int cnt, int s) {
    int rel  = (o0 >> 1) + 32;
    int base = i0 + o0;
    if (cnt == 8) return conv_block<4>(tilU, tap, rel, base, s);
    float mx = -INFINITY;
    int nb = cnt >> 4;
    for (int b = 0; b < nb; b++)
        mx = fmaxf(mx, conv_block<8>(tilU, tap, rel + 8 * b, base + 16 * b, s));
    return mx;
}

// ---- unified conv: all bands, 2 CTAs/SM, <4>/<8> only ------------------------
// chunks per signal: j=6:65, j=5:32, j=4:16, j=3:8, j=2:4, j=1:2, j=0:1 (=128)
__global__ __launch_bounds__(256, 2) void conv_kernel(const float* __restrict__ filters) {
    __shared__ float2 tile2[420];
    __shared__ float  filt[64 * 65];
    __shared__ float  red[4][64];

    int tid = threadIdx.x;
    for (int t = tid; t < 4096; t += 256)
        filt[(t >> 6) * 65 + (t & 63)] = filters[t];
    __syncthreads();

    int f = tid & 63, grp = tid >> 6;
    float tap[64];
#pragma unroll
    for (int k = 0; k < 64; k++) tap[k] = filt[f * 65 + k];

    int r = blockIdx.x;                          // 0..127
    int sig = blockIdx.y;
    int j, cb;
    if      (r < 65)  { j = 6; cb = r;       }
    else if (r < 97)  { j = 5; cb = r - 65;  }
    else if (r < 113) { j = 4; cb = r - 97;  }
    else if (r < 121) { j = 3; cb = r - 113; }
    else if (r < 125) { j = 2; cb = r - 121; }
    else if (r < 127) { j = 1; cb = r - 125; }
    else              { j = 0; cb = 0;       }

    int stride = 8 << j;
    int s = 512 << j;
    int pad = stride >> 1;
    int q0, qn;
    if (j == 6) { q0 = cb; qn = 1; }
    else {
        int c = 64 >> j;
        q0 = cb * c;
        qn = c + ((cb == (1 << j) - 1) ? 1 : 0);  // last chunk absorbs segment 65
    }
    int i0 = q0 * stride - pad;
    int nout = qn * stride;
    const float* band = d_band + sig * BAND_SPAN + band_off(j);

    int tstart2 = i0 - 64;
    int tlen2 = (nout + 64) >> 1;
    for (int m = tid; m < tlen2; m += 256) {
        int g = tstart2 + 2 * m;
        float a = (g >= 0 && g < s)         ? band[g]     : 0.0f;
        float b = (g + 1 >= 0 && g + 1 < s) ? band[g + 1] : 0.0f;
        tile2[m] = make_float2(a, b);
    }
    __syncthreads();

    const unsigned long long* tilU = (const unsigned long long*)tile2;
    float* segout = d_seg + (size_t)((sig * NBANDS + j) * NFILT + f) * 65;

    if (qn >= 3) {
        // whole segments per group (any idle groups negligible)
        for (int q = grp; q < qn; q += 4) {
            float mx = conv_run(tilU, tap, i0, q * stride, stride, s);
            segout[q0 + q] = mx;
        }
    } else if (qn == 2) {
        // groups {0,1} -> seg q0, {2,3} -> seg q0+1
        int opg = stride >> 1;                   // multiple of 16 for j>=5... j>=1
        float mx = conv_run(tilU, tap, i0, grp * opg, opg, s);
        red[grp][f] = mx;
        __syncthreads();
        if ((grp & 1) == 0) {
            float v = fmaxf(red[grp][f], red[grp | 1][f]);
            segout[q0 + (grp >> 1)] = v;
        }
    } else {  // qn == 1 (j==6): 4 groups share the segment
        int opg = stride >> 2;                   // 128 -> <8> x8
        float mx = conv_run(tilU, tap, i0, grp * opg, opg, s);
        red[grp][f] = mx;
        __syncthreads();
        if (tid < 64) {
            float v = fmaxf(fmaxf(red[0][tid], red[1][tid]),
                            fmaxf(red[2][tid], red[3][tid]));
            segout[q0] = v;
        }
    }
}

// ---------------- 4) exact top-128: two-level radix select + sort-256 ---------
__device__ __forceinline__ void select_bucket(const int* hist, int* scanbuf,
                                              int need, int tid,
                                              int* s_b, int* s_below) {
    if (tid < 256) {
        int part = 0;
#pragma unroll
        for (int i = 0; i < 16; i++) part += hist[tid * 16 + i];
        scanbuf[tid] = part;
    }
    __syncthreads();
    for (int off = 1; off < 256; off <<= 1) {
        int v = (tid >= off && tid < 256) ? scanbuf[tid - off] : 0;
        __syncthreads();
        if (tid < 256) scanbuf[tid] += v;
        __syncthreads();
    }
    if (tid < 256) {
        int incl = scanbuf[tid];
        int excl = (tid > 0) ? scanbuf[tid - 1] : 0;
        if (incl >= need && excl < need) {
            int cum = excl;
            for (int i = 0; i < 16; i++) {
                int cc = hist[tid * 16 + i];
                if (cum + cc >= need) { *s_b = tid * 16 + i; *s_below = cum; break; }
                cum += cc;
            }
        }
    }
    __syncthreads();
}

__global__ __launch_bounds__(512) void topk_kernel() {
    int j   = blockIdx.x;
    int sig = blockIdx.y;
    __shared__ unsigned hk[4096];
    __shared__ int hist[4096];
    __shared__ unsigned long long cand[1024];
    __shared__ int scanbuf[256];
    __shared__ int s_b1, s_blw1, s_b2, s_blw2, s_count;
    const float* seg = d_seg + (size_t)(sig * NBANDS + j) * NFILT * 65;
    int tid = threadIdx.x;
    const int T = 512;

    for (int t = tid; t < 4096; t += T) {
        int f = t >> 6, o = t & 63;
        float v = fmaxf(seg[f * 65 + o], seg[f * 65 + o + 1]);
        unsigned ub = __float_as_uint(v);
        ub = (ub >> 31) ? ~ub : (ub | 0x80000000u);
        hk[t] = ~ub;              // smaller hk = larger value
        hist[t] = 0;
    }
    if (tid == 0) s_count = 0;
    __syncthreads();
    for (int t = tid; t < 4096; t += T)
        atomicAdd(&hist[hk[t] >> 20], 1);
    __syncthreads();

    select_bucket(hist, scanbuf, KTOP, tid, &s_b1, &s_blw1);
    unsigned b1 = (unsigned)s_b1;
    int A = s_blw1;

    for (int t = tid; t < 4096; t += T) hist[t] = 0;
    __syncthreads();
    for (int t = tid; t < 4096; t += T)
        if ((hk[t] >> 20) == b1)
            atomicAdd(&hist[(hk[t] >> 8) & 0xFFF], 1);
    __syncthreads();
    select_bucket(hist, scanbuf, KTOP - A, tid, &s_b2, &s_blw2);
    unsigned b2 = (unsigned)s_b2;

    for (int t = tid; t < 4096; t += T) {
        unsigned key = hk[t];
        unsigned b = key >> 20;
        if (b < b1 || (b == b1 && ((key >> 8) & 0xFFF) <= b2)) {
            int pos = atomicAdd(&s_count, 1);
            if (pos < 256)
                cand[pos] = ((unsigned long long)key << 32) | (unsigned)t;
        }
    }
    __syncthreads();
    int n = s_count;
    int nsort;
    if (n <= 256) {
        nsort = 256;
        if (tid < 256 && tid >= n) cand[tid] = ~0ull;
        __syncthreads();
    } else {
        if (tid == 0) s_count = 0;
        __syncthreads();
        for (int t = tid; t < 4096; t += T) {
            if ((hk[t] >> 20) <= b1) {
                int pos = atomicAdd(&s_count, 1);
                if (pos < 1024)
                    cand[pos] = ((unsigned long long)hk[t] << 32) | (unsigned)t;
            }
        }
        __syncthreads();
        int n2 = s_count < 1024 ? s_count : 1024;
        for (int t = tid; t < 1024; t += T)
            if (t >= n2) cand[t] = ~0ull;
        nsort = 1024;
        __syncthreads();
    }

    if (nsort == 256) {
        for (int kk = 2; kk <= 256; kk <<= 1) {
            for (int jj = kk >> 1; jj > 0; jj >>= 1) {
                if (tid < 256) {
                    int ixj = tid ^ jj;
                    if (ixj > tid) {
                        bool up = ((tid & kk) == 0);
                        unsigned long long A_ = cand[tid], B_ = cand[ixj];
                        if (up ? (A_ > B_) : (A_ < B_)) { cand[tid] = B_; cand[ixj] = A_; }
                    }
                }
                __syncthreads();
            }
        }
    } else {
        for (int kk = 2; kk <= 1024; kk <<= 1) {
            for (int jj = kk >> 1; jj > 0; jj >>= 1) {
                for (int v = tid; v < 1024; v += T) {
                    int ixj = v ^ jj;
                    if (ixj > v) {
                        bool up = ((v & kk) == 0);
                        unsigned long long A_ = cand[v], B_ = cand[ixj];
                        if (up ? (A_ > B_) : (A_ < B_)) { cand[v] = B_; cand[ixj] = A_; }
                    }
                }
                __syncthreads();
            }
        }
    }

    if (tid < KTOP) {
        unsigned long long key = cand[tid];
        int idx = (int)(unsigned)key;
        int f = idx >> 6, o = idx & 63;
        float v = fmaxf(seg[f * 65 + o], seg[f * 65 + o + 1]);
        int base = (sig * NBANDS + j) * KTOP + tid;
        d_tkv[base] = v;
        d_tki[base] = idx;
    }
}

// ---------------- 5) loss ------------------------------------------------------
__global__ __launch_bounds__(128) void loss_kernel(const float* __restrict__ PT,
                                                   const float* __restrict__ PF) {
    int b = blockIdx.x;
    int j = blockIdx.y;
    int k = threadIdx.x;
    int ti = (b * NBANDS + j) * KTOP + k;
    int ri = ((b + 8) * NBANDS + j) * KTOP + k;
    float vt = d_tkv[ti]; int it = d_tki[ti];
    float vr = d_tkv[ri]; int ir = d_tki[ri];
    int tmt = it & 63, cht = it >> 6;
    int tmr = ir & 63, chr_ = ir >> 6;
    const float* ptt  = PT + tmt * 128;
    const float* ptr_ = PT + tmr * 128;
    const float* pft  = PF + cht * 128;
    const float* pfr  = PF + chr_ * 128;
    float ssum = 0.0f;
#pragma unroll 4
    for (int d = 0; d < 128; d++) {
        ssum += fabsf(vt * ptt[d] - vr * ptr_[d]);
        ssum += fabsf(pft[d] - pfr[d]);
    }
    __shared__ float rs[128];
    rs[k] = ssum;
    __syncthreads();
    for (int st = 64; st > 0; st >>= 1) {
        if (k < st) rs[k] += rs[k + st];
        __syncthreads();
    }
    if (k == 0) d_partial[b * NBANDS + j] = rs[0];
}

__global__ void final_kernel(float* out) {
    if (threadIdx.x == 0) {
        float s = 0.0f;
        for (int i = 0; i < PBLOCKS; i++) s += d_partial[i];
        out[0] = s / 1835008.0f;   // 8 * 128 * 256 * 7
    }
}

// ---------------- launch ------------------------------------------------------
extern "C" void kernel_launch(void* const* d_in, const int* in_sizes, int n_in,
                              void* d_out, int out_size) {
    const float* target  = (const float*)d_in[0];
    const float* recon   = (const float*)d_in[1];
    const float* filters = (const float*)d_in[2];
    const float* PT      = (const float*)d_in[3];
    const float* PF      = (const float*)d_in[4];
    float* out = (float*)d_out;

    const int FFT_SMEM = (DATA_PAD + 8736) * sizeof(float2);   // 209664 B
    cudaFuncSetAttribute(fwd_fft_kernel,
                         cudaFuncAttributeMaxDynamicSharedMemorySize, FFT_SMEM);
    cudaFuncSetAttribute(inv_band_kernel,
                         cudaFuncAttributeMaxDynamicSharedMemorySize, FFT_SMEM);

    tw_init_kernel<<<32, 512>>>();                                   // 1
    fwd_fft_kernel<<<NSIG, 1024, FFT_SMEM>>>(target, recon);         // 2
    inv_band_kernel<<<dim3(NBANDS, NSIG), 1024, FFT_SMEM>>>();       // 3
    conv_kernel<<<dim3(NCHU, NSIG), 256>>>(filters);                 // 4 (profiled)
    topk_kernel<<<dim3(NBANDS, NSIG), 512>>>();                      // 5
    loss_kernel<<<dim3(8, NBANDS), 128>>>(PT, PF);                   // 6
    final_kernel<<<1, 32>>>(out);                                    // 7
}

// round 17
// speedup vs baseline: 1.6782x; 1.6782x over previous
#include <cuda_runtime.h>
#include <math.h>
#include <stdint.h>

#define NSAMP   32768
#define NSIG    16          // 8 target + 8 recon
#define NBANDS  7
#define NFILT   64
#define KTOP    128
#define BAND_SPAN 65024     // sum of band sizes per signal
#define PBLOCKS 56
#define NCHB    132         // chunks/signal: j2:5 j3:9 j4:17 j5:33 j6:65 + j1:2 + j0:1

// multi-scale padding: conflict-free strided smem access for all FFT stages
#define PADI(i) ((i) + ((i) >> 4) + ((i) >> 8))

// ---------------- scratch (static device globals; no allocation) -------------
__device__ float2 d_X[NSIG * 16384];                 // rfft bins per signal
__device__ float  d_band[NSIG * BAND_SPAN];          // all band time signals
__device__ float  d_seg [NSIG * NBANDS * NFILT * 65];// segment maxima (65 segs)
__device__ float  d_tkv [NSIG * NBANDS * KTOP];      // top-k values
__device__ int    d_tki [NSIG * NBANDS * KTOP];      // top-k flat indices
__device__ float  d_partial[PBLOCKS];
__device__ float2 d_tab[16384];                      // e^{+2pi i r/32768}

__device__ __forceinline__ int band_off(int j) { return 512 * ((1 << j) - 1); }

__device__ __forceinline__ float2 cmul_s(float2 a, float2 w, float sign) {
    float wy = sign * w.y;
    return make_float2(a.x * w.x - a.y * wy, a.x * wy + a.y * w.x);
}

// ---------------- 0) twiddle table init ---------------------------------------
__global__ void tw_init_kernel() {
    int idx = blockIdx.x * blockDim.x + threadIdx.x;
    if (idx < 16384) {
        float s_, c_;
        sincospif((float)idx / 16384.0f, &s_, &c_);   // 2*pi*idx/32768
        d_tab[idx] = make_float2(c_, s_);
    }
}

// ------------- fused radix-4 (2x radix-2) in-place DIT FFT over smem ----------
__device__ __forceinline__ void fft_fused(float2* a, const float2* tw,
                                          int n, int logn, float sign,
                                          int tid, int T) {
    int st = 1;
    if (logn & 1) {
        int nb = n >> 1;
        for (int idx = tid; idx < nb; idx += T) {
            int i0 = idx << 1;
            int p0 = PADI(i0), p1 = PADI(i0 + 1);
            float2 u = a[p0], v = a[p1];
            a[p0] = make_float2(u.x + v.x, u.y + v.y);
            a[p1] = make_float2(u.x - v.x, u.y - v.y);
        }
        __syncthreads();
        st = 2;
    }
    int nq = n >> 2;
    for (; st < logn; st += 2) {
        int h = 1 << (st - 1);
        int shift = logn - st;
        for (int q = tid; q < nq; q += T) {
            int jj = q & (h - 1);
            int i0 = ((q >> (st - 1)) << (st + 1)) + jj;
            int p0 = PADI(i0), p1 = PADI(i0 + h);
            int p2 = PADI(i0 + 2 * h), p3 = PADI(i0 + 3 * h);
            float2 x0 = a[p0], x1 = a[p1], x2 = a[p2], x3 = a[p3];
            float2 wa = tw[PADI(jj << shift)];
            float2 wb = tw[PADI(jj << (shift - 1))];
            float2 t1 = cmul_s(x1, wa, sign);
            float2 t3 = cmul_s(x3, wa, sign);
            float2 y0 = make_float2(x0.x + t1.x, x0.y + t1.y);
            float2 y1 = make_float2(x0.x - t1.x, x0.y - t1.y);
            float2 y2 = make_float2(x2.x + t3.x, x2.y + t3.y);
            float2 y3 = make_float2(x2.x - t3.x, x2.y - t3.y);
            float2 u2 = cmul_s(y2, wb, sign);
            float2 u3 = cmul_s(y3, wb, sign);
            float2 v3 = make_float2(-sign * u3.y, sign * u3.x);
            a[p0] = make_float2(y0.x + u2.x, y0.y + u2.y);
            a[p2] = make_float2(y0.x - u2.x, y0.y - u2.y);
            a[p1] = make_float2(y1.x + v3.x, y1.y + v3.y);
            a[p3] = make_float2(y1.x - v3.x, y1.y - v3.y);
        }
        __syncthreads();
    }
}

// load twiddles for size-n FFT from the global table (stride = 32768/n)
__device__ __forceinline__ void load_twiddles(float2* tw, int n, int tid, int T) {
    int st = 32768 / n;
    for (int r = tid; r < (n >> 1); r += T)
        tw[PADI(r)] = d_tab[r * st];
}

// ---------------- 1) forward rfft of each 32768-sample signal -----------------
extern __shared__ float2 smem_c[];
#define DATA_PAD 17472

__global__ __launch_bounds__(1024) void fwd_fft_kernel(const float* __restrict__ tgt,
                                                       const float* __restrict__ rec) {
    const int m = 16384, logm = 14;
    int sig = blockIdx.x;
    const float* x = (sig < 8) ? (tgt + (size_t)sig * NSAMP)
                               : (rec + (size_t)(sig - 8) * NSAMP);
    float2* data = smem_c;
    float2* tw   = smem_c + DATA_PAD;
    int tid = threadIdx.x, T = blockDim.x;

    load_twiddles(tw, m, tid, T);
    for (int t = tid; t < m; t += T) {
        int r = (int)(__brev((unsigned)t) >> (32 - logm));
        data[PADI(r)] = make_float2(x[2 * t], x[2 * t + 1]);
    }
    __syncthreads();
    fft_fused(data, tw, m, logm, -1.0f, tid, T);

    for (int k = tid; k < m; k += T) {
        float2 zk = data[PADI(k)];
        float2 zm = data[PADI((m - k) & (m - 1))];
        float2 E = make_float2(0.5f * (zk.x + zm.x), 0.5f * (zk.y - zm.y));
        float2 D = make_float2(0.5f * (zk.x - zm.x), 0.5f * (zk.y + zm.y));
        float2 ph = d_tab[k];                     // e^{+2pi i k/32768}
        float c_ = ph.x, s_ = -ph.y;              // e^{-2pi i k/32768}
        float2 miD = make_float2(D.y, -D.x);
        float tr = miD.x * c_ - miD.y * s_;
        float ti = miD.x * s_ + miD.y * c_;
        d_X[sig * 16384 + k] = make_float2(E.x + tr, E.y + ti);
    }
}

// ---------------- 2) per-band inverse rfft (ortho-scaled) ---------------------
__global__ __launch_bounds__(1024) void inv_band_kernel() {
    int j   = blockIdx.x;
    int sig = blockIdx.y;
    int m = 256 << j, logm = 8 + j;
    int lo = (j == 0) ? 0 : (m >> 1);
    int s2 = 2 * m;
    const float2* X = d_X + sig * 16384;
    float2* data = smem_c;
    float2* tw   = smem_c + DATA_PAD;
    int tid = threadIdx.x, T = blockDim.x;
    int pst = 16384 / m;                          // phase stride for e^{2pi i k/s2}

    load_twiddles(tw, m, tid, T);
    for (int k = tid; k < m; k += T) {
        float2 Xk = (k >= lo) ? X[k] : make_float2(0.f, 0.f);
        int mk = m - k;
        float2 Xm = (mk >= lo && mk < m) ? X[mk] : make_float2(0.f, 0.f);
        float2 E = make_float2(0.5f * (Xk.x + Xm.x), 0.5f * (Xk.y - Xm.y));
        float2 D = make_float2(0.5f * (Xk.x - Xm.x), 0.5f * (Xk.y + Xm.y));
        float2 ph = d_tab[k * pst];               // e^{+2pi i k/s2}
        float c_ = ph.x, s_ = ph.y;
        float2 O = make_float2(D.x * c_ - D.y * s_, D.x * s_ + D.y * c_);
        float2 Z = make_float2(E.x - O.y, E.y + O.x);
        int r = (int)(__brev((unsigned)k) >> (32 - logm));
        data[PADI(r)] = Z;
    }
    __syncthreads();
    fft_fused(data, tw, m, logm, +1.0f, tid, T);

    float scale = 2.0f * rsqrtf((float)s2 * (float)NSAMP);
    float* out = d_band + sig * BAND_SPAN + band_off(j);
    for (int t = tid; t < m; t += T) {
        float2 z = data[PADI(t)];
        out[2 * t]     = scale * z.x;
        out[2 * t + 1] = scale * z.y;
    }
}

// ---------------- 3) 64-tap FIR + segment maxima, packed f32x2 ----------------
// Taps in REGISTERS (one row per thread), duplicated to f32x2 via mov.b64.
#define FMA2(acc, a, b) asm("fma.rn.f32x2 %0, %1, %2, %3;" \
    : "=l"(acc) : "l"(a), "l"(b), "l"(acc))
#define DUP2(d, x) asm("mov.b64 %0, {%1, %1};" : "=l"(d) : "r"(__float_as_uint(x)))

template<int P>
__device__ __forceinline__ float conv_block(const unsigned long long* __restrict__ tilU,
                                            const float* __restrict__ tap,
                                            int rel, int base, int s) {
    unsigned long long W[P + 1], S[P], T[P + 1];
#pragma unroll
    for (int m = 0; m <= P; m++) W[m] = tilU[rel - 1 + m];
#pragma unroll
    for (int p = 0; p < P; p++) S[p] = 0ull;
#pragma unroll
    for (int p = 0; p <= P; p++) T[p] = 0ull;
#pragma unroll
    for (int h = 0; h < 32; h++) {
        unsigned long long te, to;
        DUP2(te, tap[2 * h]);
        DUP2(to, tap[2 * h + 1]);
#pragma unroll
        for (int p = 0; p < P; p++) FMA2(S[p], W[p + 1], te);
#pragma unroll
        for (int p = 0; p <= P; p++) FMA2(T[p], W[p], to);
        if (h < 31) {
#pragma unroll
            for (int m = P; m >= 1; m--) W[m] = W[m - 1];
            W[0] = tilU[rel - h - 2];
        }
    }
    float mx = -INFINITY;
#pragma unroll
    for (int p = 0; p < P; p++) {
        float2 sv = *(float2*)&S[p];
        float2 ta = *(float2*)&T[p];
        float2 tb = *(float2*)&T[p + 1];
        float v0 = sv.x + ta.y;
        float v1 = sv.y + tb.x;
        int ia = base + 2 * p;
        if (ia < 0 || ia >= s)         v0 = -INFINITY;
        if (ia + 1 < 0 || ia + 1 >= s) v1 = -INFINITY;
        mx = fmaxf(mx, fmaxf(v0, v1));
    }
    return mx;
}

// runner: cnt == 8 (j<=2 cases) or a multiple of 16
__device__ __forceinline__ float conv_run_big(const unsigned long long* __restrict__ tilU,
                                              const float* __restrict__ tap,
                                              int i0, int o0, int cnt, int s) {
    int rel  = (o0 >> 1) + 32;
    int base = i0 + o0;
    if (cnt == 8) return conv_block<4>(tilU, tap, rel, base, s);
    float mx = -INFINITY;
    int nb = cnt >> 4;
    for (int b = 0; b < nb; b++)
        mx = fmaxf(mx, conv_block<8>(tilU, tap, rel + 8 * b, base + 16 * b, s));
    return mx;
}

// ---- all bands, 2 CTAs/SM, <4>/<8> only --------------------------------------
// r: 0..4 j2, 5..13 j3, 14..30 j4, 31..63 j5, 64..128 j6, 129..130 j1, 131 j0
__global__ __launch_bounds__(256, 2) void conv_big_kernel(const float* __restrict__ filters) {
    __shared__ float2 tile2[300];
    __shared__ float  filt[64 * 65];
    __shared__ float  red[4][64];

    int tid = threadIdx.x;
    for (int t = tid; t < 4096; t += 256)
        filt[(t >> 6) * 65 + (t & 63)] = filters[t];
    __syncthreads();

    int f = tid & 63, grp = tid >> 6;
    float tap[64];
#pragma unroll
    for (int k = 0; k < 64; k++) tap[k] = filt[f * 65 + k];

    int r = blockIdx.x;                          // 0..131
    int sig = blockIdx.y;
    int j, cb;
    if      (r >= 131) { j = 0; cb = 0;       }
    else if (r >= 129) { j = 1; cb = r - 129; }
    else if (r >= 64)  { j = 6; cb = r - 64;  }
    else if (r >= 31)  { j = 5; cb = r - 31;  }
    else if (r >= 14)  { j = 4; cb = r - 14;  }
    else if (r >= 5)   { j = 3; cb = r - 5;   }
    else               { j = 2; cb = r;       }

    int c = 64 >> j;
    int q0 = cb * c;
    int qn = 65 - q0; if (qn > c) qn = c;
    if (j == 1 && cb == 1) qn = 33;              // absorb segment 65
    if (j == 0) qn = 65;
    int stride = 8 << j;
    int s = 512 << j;
    int pad = stride >> 1;
    int i0 = q0 * stride - pad;
    int nout = qn * stride;
    const float* band = d_band + sig * BAND_SPAN + band_off(j);

    int tstart2 = i0 - 64;
    int tlen2 = (nout + 64) >> 1;
    for (int m = tid; m < tlen2; m += 256) {
        int g = tstart2 + 2 * m;
        float a = (g >= 0 && g < s)         ? band[g]     : 0.0f;
        float b = (g + 1 >= 0 && g + 1 < s) ? band[g + 1] : 0.0f;
        tile2[m] = make_float2(a, b);
    }
    __syncthreads();

    const unsigned long long* tilU = (const unsigned long long*)tile2;
    float* segout = d_seg + (size_t)((sig * NBANDS + j) * NFILT + f) * 65;

    if (qn >= 4) {
        for (int q = grp; q < qn; q += 4) {
            float mx = conv_run_big(tilU, tap, i0, q * stride, stride, s);
            segout[q0 + q] = mx;
        }
    } else {
        // qn == 1 or 2 (includes j=2 tail with opg==8)
        int opg = (qn * stride) >> 2;
        float mx = conv_run_big(tilU, tap, i0, grp * opg, opg, s);
        red[grp][f] = mx;
        __syncthreads();
        if (qn == 1) {
            if (tid < 64) {
                float v = fmaxf(fmaxf(red[0][tid], red[1][tid]),
                                fmaxf(red[2][tid], red[3][tid]));
                segout[q0] = v;
            }
        } else {  // qn == 2
            if ((grp & 1) == 0) {
                float v = fmaxf(red[grp][f], red[grp | 1][f]);
                segout[q0 + (grp >> 1)] = v;
            }
        }
    }
}

// ---------------- 4) exact top-128: two-level radix select + sort-256 ---------
__device__ __forceinline__ void select_bucket(const int* hist, int* scanbuf,
                                              int need, int tid,
                                              int* s_b, int* s_below) {
    if (tid < 256) {
        int part = 0;
#pragma unroll
        for (int i = 0; i < 16; i++) part += hist[tid * 16 + i];
        scanbuf[tid] = part;
    }
    __syncthreads();
    for (int off = 1; off < 256; off <<= 1) {
        int v = (tid >= off && tid < 256) ? scanbuf[tid - off] : 0;
        __syncthreads();
        if (tid < 256) scanbuf[tid] += v;
        __syncthreads();
    }
    if (tid < 256) {
        int incl = scanbuf[tid];
        int excl = (tid > 0) ? scanbuf[tid - 1] : 0;
        if (incl >= need && excl < need) {
            int cum = excl;
            for (int i = 0; i < 16; i++) {
                int cc = hist[tid * 16 + i];
                if (cum + cc >= need) { *s_b = tid * 16 + i; *s_below = cum; break; }
                cum += cc;
            }
        }
    }
    __syncthreads();
}

__global__ __launch_bounds__(512) void topk_kernel() {
    int j   = blockIdx.x;
    int sig = blockIdx.y;
    __shared__ unsigned hk[4096];
    __shared__ int hist[4096];
    __shared__ unsigned long long cand[1024];
    __shared__ int scanbuf[256];
    __shared__ int s_b1, s_blw1, s_b2, s_blw2, s_count;
    const float* seg = d_seg + (size_t)(sig * NBANDS + j) * NFILT * 65;
    int tid = threadIdx.x;
    const int T = 512;

    for (int t = tid; t < 4096; t += T) {
        int f = t >> 6, o = t & 63;
        float v = fmaxf(seg[f * 65 + o], seg[f * 65 + o + 1]);
        unsigned ub = __float_as_uint(v);
        ub = (ub >> 31) ? ~ub : (ub | 0x80000000u);
        hk[t] = ~ub;              // smaller hk = larger value
        hist[t] = 0;
    }
    if (tid == 0) s_count = 0;
    __syncthreads();
    for (int t = tid; t < 4096; t += T)
        atomicAdd(&hist[hk[t] >> 20], 1);
    __syncthreads();

    select_bucket(hist, scanbuf, KTOP, tid, &s_b1, &s_blw1);
    unsigned b1 = (unsigned)s_b1;
    int A = s_blw1;

    for (int t = tid; t < 4096; t += T) hist[t] = 0;
    __syncthreads();
    for (int t = tid; t < 4096; t += T)
        if ((hk[t] >> 20) == b1)
            atomicAdd(&hist[(hk[t] >> 8) & 0xFFF], 1);
    __syncthreads();
    select_bucket(hist, scanbuf, KTOP - A, tid, &s_b2, &s_blw2);
    unsigned b2 = (unsigned)s_b2;

    for (int t = tid; t < 4096; t += T) {
        unsigned key = hk[t];
        unsigned b = key >> 20;
        if (b < b1 || (b == b1 && ((key >> 8) & 0xFFF) <= b2)) {
            int pos = atomicAdd(&s_count, 1);
            if (pos < 256)
                cand[pos] = ((unsigned long long)key << 32) | (unsigned)t;
        }
    }
    __syncthreads();
    int n = s_count;
    int nsort;
    if (n <= 256) {
        nsort = 256;
        if (tid < 256 && tid >= n) cand[tid] = ~0ull;
        __syncthreads();
    } else {
        if (tid == 0) s_count = 0;
        __syncthreads();
        for (int t = tid; t < 4096; t += T) {
            if ((hk[t] >> 20) <= b1) {
                int pos = atomicAdd(&s_count, 1);
                if (pos < 1024)
                    cand[pos] = ((unsigned long long)hk[t] << 32) | (unsigned)t;
            }
        }
        __syncthreads();
        int n2 = s_count < 1024 ? s_count : 1024;
        for (int t = tid; t < 1024; t += T)
            if (t >= n2) cand[t] = ~0ull;
        nsort = 1024;
        __syncthreads();
    }

    if (nsort == 256) {
        for (int kk = 2; kk <= 256; kk <<= 1) {
            for (int jj = kk >> 1; jj > 0; jj >>= 1) {
                if (tid < 256) {
                    int ixj = tid ^ jj;
                    if (ixj > tid) {
                        bool up = ((tid & kk) == 0);
                        unsigned long long A_ = cand[tid], B_ = cand[ixj];
                        if (up ? (A_ > B_) : (A_ < B_)) { cand[tid] = B_; cand[ixj] = A_; }
                    }
                }
                __syncthreads();
            }
        }
    } else {
        for (int kk = 2; kk <= 1024; kk <<= 1) {
            for (int jj = kk >> 1; jj > 0; jj >>= 1) {
                for (int v = tid; v < 1024; v += T) {
                    int ixj = v ^ jj;
                    if (ixj > v) {
                        bool up = ((v & kk) == 0);
                        unsigned long long A_ = cand[v], B_ = cand[ixj];
                        if (up ? (A_ > B_) : (A_ < B_)) { cand[v] = B_; cand[ixj] = A_; }
                    }
                }
                __syncthreads();
            }
        }
    }

    if (tid < KTOP) {
        unsigned long long key = cand[tid];
        int idx = (int)(unsigned)key;
        int f = idx >> 6, o = idx & 63;
        float v = fmaxf(seg[f * 65 + o], seg[f * 65 + o + 1]);
        int base = (sig * NBANDS + j) * KTOP + tid;
        d_tkv[base] = v;
        d_tki[base] = idx;
    }
}

// ---------------- 5) loss ------------------------------------------------------
__global__ __launch_bounds__(128) void loss_kernel(const float* __restrict__ PT,
                                                   const float* __restrict__ PF) {
    int b = blockIdx.x;
    int j = blockIdx.y;
    int k = threadIdx.x;
    int ti = (b * NBANDS + j) * KTOP + k;
    int ri = ((b + 8) * NBANDS + j) * KTOP + k;
    float vt = d_tkv[ti]; int it = d_tki[ti];
    float vr = d_tkv[ri]; int ir = d_tki[ri];
    int tmt = it & 63, cht = it >> 6;
    int tmr = ir & 63, chr_ = ir >> 6;
    const float* ptt  = PT + tmt * 128;
    const float* ptr_ = PT + tmr * 128;
    const float* pft  = PF + cht * 128;
    const float* pfr  = PF + chr_ * 128;
    float ssum = 0.0f;
#pragma unroll 4
    for (int d = 0; d < 128; d++) {
        ssum += fabsf(vt * ptt[d] - vr * ptr_[d]);
        ssum += fabsf(pft[d] - pfr[d]);
    }
    __shared__ float rs[128];
    rs[k] = ssum;
    __syncthreads();
    for (int st = 64; st > 0; st >>= 1) {
        if (k < st) rs[k] += rs[k + st];
        __syncthreads();
    }
    if (k == 0) d_partial[b * NBANDS + j] = rs[0];
}

__global__ void final_kernel(float* out) {
    if (threadIdx.x == 0) {
        float s = 0.0f;
        for (int i = 0; i < PBLOCKS; i++) s += d_partial[i];
        out[0] = s / 1835008.0f;   // 8 * 128 * 256 * 7
    }
}

// ---------------- launch ------------------------------------------------------
extern "C" void kernel_launch(void* const* d_in, const int* in_sizes, int n_in,
                              void* d_out, int out_size) {
    const float* target  = (const float*)d_in[0];
    const float* recon   = (const float*)d_in[1];
    const float* filters = (const float*)d_in[2];
    const float* PT      = (const float*)d_in[3];
    const float* PF      = (const float*)d_in[4];
    float* out = (float*)d_out;

    const int FFT_SMEM = (DATA_PAD + 8736) * sizeof(float2);   // 209664 B
    cudaFuncSetAttribute(fwd_fft_kernel,
                         cudaFuncAttributeMaxDynamicSharedMemorySize, FFT_SMEM);
    cudaFuncSetAttribute(inv_band_kernel,
                         cudaFuncAttributeMaxDynamicSharedMemorySize, FFT_SMEM);

    tw_init_kernel<<<32, 512>>>();                                   // 1
    fwd_fft_kernel<<<NSIG, 1024, FFT_SMEM>>>(target, recon);         // 2
    inv_band_kernel<<<dim3(NBANDS, NSIG), 1024, FFT_SMEM>>>();       // 3
    conv_big_kernel<<<dim3(NCHB, NSIG), 256>>>(filters);             // 4 (profiled)
    topk_kernel<<<dim3(NBANDS, NSIG), 512>>>();                      // 5
    loss_kernel<<<dim3(8, NBANDS), 128>>>(PT, PF);                   // 6
    final_kernel<<<1, 32>>>(out);                                    // 7
}